// round 16
// baseline (speedup 1.0000x reference)
#include <cuda_runtime.h>
#include <cuda_fp16.h>
#include <cstdint>

// ---------------- problem constants ----------------
#define CIN 128
#define COUT 256
#define NPIX (8 * 128 * 128)
#define M_TOTAL 32768                      // 8 * 64 * 64
#define K_TOTAL 1152                       // 9 * 128
#define FEATS_OUT_ELEMS ((size_t)M_TOTAL * COUT)
#define COORD_OUT_ELEMS ((size_t)M_TOTAL * 3)

// ---------------- GEMM config ----------------
#define BM 128
#define BN 256
#define NSTAGE 6
#define NTHREADS 512          // 16 warps: 4 m x 4 n, warp tile 32x64

// smem stage: A 128 rows x 64B, then B 256 rows x 64B
// phys16B(chunk) = (chunk ^ ((row>>1)&3)) * 16
#define OFF_B 8192
#define STAGE_BYTES 24576u
#define SMEM_TOTAL (NSTAGE * STAGE_BYTES)   // 147456; 1 CTA/SM, 128 regs/thread

// ---------------- device scratch ----------------
__device__ __align__(16) __half g_Wh[COUT * K_TOTAL];            // [n][k] fp16
__device__ __align__(16) __half g_Ah[(size_t)NPIX * CIN];        // feats fp16

// ---------------- helpers ----------------
__device__ __forceinline__ uint32_t smem_u32(const void* p) {
    uint32_t a;
    asm("{ .reg .u64 t; cvta.to.shared.u64 t, %1; cvt.u32.u64 %0, t; }" : "=r"(a) : "l"(p));
    return a;
}
__device__ __forceinline__ void cp_async16(uint32_t dst, const void* src) {
    asm volatile("cp.async.cg.shared.global [%0], [%1], 16;" :: "r"(dst), "l"(src) : "memory");
}
__device__ __forceinline__ void cp_async16z(uint32_t dst, const void* src, uint32_t src_size) {
    asm volatile("cp.async.cg.shared.global [%0], [%1], 16, %2;"
                 :: "r"(dst), "l"(src), "r"(src_size) : "memory");
}
__device__ __forceinline__ void cp_commit() {
    asm volatile("cp.async.commit_group;" ::: "memory");
}
template <int N>
__device__ __forceinline__ void cp_wait() {
    asm volatile("cp.async.wait_group %0;" :: "n"(N) : "memory");
}
__device__ __forceinline__ void ldsm_x4(uint32_t& r0, uint32_t& r1, uint32_t& r2, uint32_t& r3,
                                        uint32_t addr) {
    asm volatile("ldmatrix.sync.aligned.m8n8.x4.shared.b16 {%0,%1,%2,%3}, [%4];"
                 : "=r"(r0), "=r"(r1), "=r"(r2), "=r"(r3) : "r"(addr));
}
__device__ __forceinline__ void mma16816(float* c, const uint32_t* a, uint32_t b0, uint32_t b1) {
    asm volatile("mma.sync.aligned.m16n8k16.row.col.f32.f16.f16.f32 "
                 "{%0,%1,%2,%3}, {%4,%5,%6,%7}, {%8,%9}, {%0,%1,%2,%3};"
                 : "+f"(c[0]), "+f"(c[1]), "+f"(c[2]), "+f"(c[3])
                 : "r"(a[0]), "r"(a[1]), "r"(a[2]), "r"(a[3]), "r"(b0), "r"(b1));
}

// ---------------- fused prep: A fp32->fp16 stream + W transpose + coords ----------------
#define A4_BLOCKS 16384
#define W_BLOCKS ((K_TOTAL / 32) * (COUT / 32))    // 288
#define C_BLOCKS (M_TOTAL / 256)                   // 128
__global__ __launch_bounds__(256)
void prep_kernel(const float* __restrict__ feats, const float* __restrict__ w,
                 const float* __restrict__ alpha, float* __restrict__ out) {
    __shared__ float tile[32][33];
    if (blockIdx.x < A4_BLOCKS) {
        size_t i4 = (size_t)blockIdx.x * 256 + threadIdx.x;
        float4 v = reinterpret_cast<const float4*>(feats)[i4];
        __half2 h0 = __floats2half2_rn(v.x, v.y);
        __half2 h1 = __floats2half2_rn(v.z, v.w);
        reinterpret_cast<uint2*>(g_Ah)[i4] =
            make_uint2(*reinterpret_cast<uint32_t*>(&h0), *reinterpret_cast<uint32_t*>(&h1));
    } else if (blockIdx.x < A4_BLOCKS + W_BLOCKS) {
        const int bid = blockIdx.x - A4_BLOCKS;
        const int kt = bid % (K_TOTAL / 32);
        const int nt = bid / (K_TOTAL / 32);
        const int ty = threadIdx.x >> 5, tx = threadIdx.x & 31;
        #pragma unroll
        for (int j = 0; j < 4; ++j)
            tile[ty + j * 8][tx] = w[(size_t)(kt * 32 + ty + j * 8) * COUT + nt * 32 + tx];
        __syncthreads();
        #pragma unroll
        for (int j = 0; j < 4; ++j) {
            const int nr = nt * 32 + ty + j * 8;
            const int k  = kt * 32 + tx;
            g_Wh[(size_t)nr * K_TOTAL + k] = __float2half_rn(tile[tx][ty + j * 8]);
        }
    } else {
        const int p = (blockIdx.x - A4_BLOCKS - W_BLOCKS) * 256 + threadIdx.x;
        float* row = out + FEATS_OUT_ELEMS + (size_t)p * 3;
        row[0] = (float)(p >> 12);
        row[1] = (float)((p & 4095) >> 6);
        row[2] = (float)(p & 63);
        if (p == 0)
            out[FEATS_OUT_ELEMS + COORD_OUT_ELEMS] = alpha[0];
    }
}

// ---------------- main GEMM kernel ----------------
__global__ __launch_bounds__(NTHREADS)
void conv_mma_kernel(float* __restrict__ out)
{
    extern __shared__ char smem[];
    const uint32_t sb = smem_u32(smem);
    const int tid = threadIdx.x;
    const int w = tid >> 5, l = tid & 31;
    const int mblk = blockIdx.x;
    const int wm = w & 3, wn = w >> 2;      // 4m x 4n, warp tile 32x64

    // ---- A loader: thread -> row tid>>2, 16B seg tid&3 (A tile 128x64B)
    const int arow = tid >> 2;
    const int lseg = tid & 3;
    const int p    = mblk * 128 + arow;
    const int ab   = p >> 12;
    const int aoy  = ((p & 4095) >> 6) << 1;
    const int aox  = (p & 63) << 1;
    const uint32_t a_dst = sb + arow * 64 + (uint32_t)((lseg ^ ((arow >> 1) & 3)) * 16);

    // ---- B loader: thread -> row tid>>1 (0..255), k-half lh = tid&1 (16 k = 32B)
    const int brow = tid >> 1;
    const int lh   = tid & 1;
    const int brs  = (brow >> 1) & 3;
    const uint32_t b_dst0 = sb + OFF_B + brow * 64 + (uint32_t)(((2 * lh)     ^ brs) * 16);
    const uint32_t b_dst1 = sb + OFF_B + brow * 64 + (uint32_t)(((2 * lh + 1) ^ brs) * 16);

    // A source base + validity for a tap
    auto tap_a = [&](int tap, const __half*& abase, uint32_t& vs) {
        const int dyr = (tap * 11) >> 5;             // tap / 3, exact for 0..8
        const int iy = aoy + dyr - 1;
        const int ix = aox + (tap - dyr * 3) - 1;
        const bool valid = ((unsigned)iy < 128u) && ((unsigned)ix < 128u);
        vs = valid ? 16u : 0u;
        const int cy = valid ? iy : 0, cx = valid ? ix : 0;
        abase = g_Ah + ((size_t)(((ab << 7) + cy) << 7) + cx) * CIN + lseg * 8;
    };
    // bbase carries tap*128 + lh*16 already; kc in elements
    auto issue = [&](const __half* abase, uint32_t vs, const __half* bbase,
                     int kc, uint32_t soff) {
        cp_async16z(a_dst + soff, abase + kc, vs);
        cp_async16(b_dst0 + soff, bbase + kc);
        cp_async16(b_dst1 + soff, bbase + kc + 8);
    };

    float acc[2][8][4];
    #pragma unroll
    for (int i = 0; i < 2; ++i)
        #pragma unroll
        for (int j = 0; j < 8; ++j)
            #pragma unroll
            for (int q = 0; q < 4; ++q) acc[i][j][q] = 0.f;

    // ---- ldsm addressing ----
    const int arow_l = wm * 32 + (l & 15);
    const int a_rs   = (arow_l >> 1) & 3;
    const uint32_t a_base0 = sb + arow_l * 64;
    const int brow_l = wn * 64 + ((l >> 4) << 3) + (l & 7);
    const int b_rs   = (brow_l >> 1) & 3;          // invariant under +16 rows
    const uint32_t b_base0 = sb + OFF_B + brow_l * 64;
    uint32_t a_off[2], b_off[2];
    #pragma unroll
    for (int k16 = 0; k16 < 2; ++k16) {
        a_off[k16] = (uint32_t)(((k16 * 2 + (l >> 4)) ^ a_rs) * 16);
        b_off[k16] = (uint32_t)(((k16 * 2 + ((l >> 3) & 1)) ^ b_rs) * 16);
    }

    // compute one chunk at stage offset soff
    auto compute_chunk = [&](uint32_t soff) {
        #pragma unroll
        for (int k16 = 0; k16 < 2; ++k16) {
            uint32_t af[2][4], bh[4][4];
            ldsm_x4(af[0][0], af[0][1], af[0][2], af[0][3],
                    a_base0 + a_off[k16] + soff);
            ldsm_x4(af[1][0], af[1][1], af[1][2], af[1][3],
                    a_base0 + 16 * 64 + a_off[k16] + soff);
            #pragma unroll
            for (int np = 0; np < 4; ++np)
                ldsm_x4(bh[np][0], bh[np][1], bh[np][2], bh[np][3],
                        b_base0 + np * (16 * 64) + b_off[k16] + soff);
            #pragma unroll
            for (int np = 0; np < 4; ++np)
                #pragma unroll
                for (int mt = 0; mt < 2; ++mt)
                    #pragma unroll
                    for (int sub = 0; sub < 2; ++sub)
                        mma16816(acc[mt][np * 2 + sub], af[mt],
                                 bh[np][sub * 2], bh[np][sub * 2 + 1]);
        }
    };

    // ---- prologue: tap 0, chunks 0..3 into stages 0..3 ----
    const __half* apf; uint32_t vpf;
    tap_a(0, apf, vpf);
    const __half* bpf = g_Wh + (size_t)brow * K_TOTAL + lh * 16;
    issue(apf, vpf, bpf, 0,  0);                cp_commit();
    issue(apf, vpf, bpf, 32, STAGE_BYTES);      cp_commit();
    issue(apf, vpf, bpf, 64, 2 * STAGE_BYTES);  cp_commit();
    issue(apf, vpf, bpf, 96, 3 * STAGE_BYTES);  cp_commit();

    // ---- main loop: 3 groups x 6 pairs (12 chunks each); stage = chunk%6 ----
    #pragma unroll 1
    for (int g = 0; g < 3; ++g) {
        #pragma unroll
        for (int pp = 0; pp < 6; ++pp) {
            cp_wait<2>();
            __syncthreads();

            const bool have = (pp < 4) || (g < 2);
            if ((pp & 1) == 0) {   // prefetch tap changes every other pair
                if (have) {
                    const int tap_pf = 3 * g + (pp + 2) / 2;
                    tap_a(tap_pf, apf, vpf);
                    bpf = g_Wh + (size_t)brow * K_TOTAL + (size_t)tap_pf * 128 + lh * 16;
                }
            }
            {
                const int kc0 = ((2 * pp + 4) & 3) * 32;
                const uint32_t s0 = (uint32_t)((2 * pp + 4) % 6) * STAGE_BYTES;
                const uint32_t s1 = (uint32_t)((2 * pp + 5) % 6) * STAGE_BYTES;
                if (have) issue(apf, vpf, bpf, kc0, s0);
                cp_commit();
                if (have) issue(apf, vpf, bpf, kc0 + 32, s1);
                cp_commit();
            }

            compute_chunk((uint32_t)((2 * pp) % 6) * STAGE_BYTES);
            compute_chunk((uint32_t)((2 * pp + 1) % 6) * STAGE_BYTES);
        }
    }

    // ---- epilogue ----
    const int row_base = mblk * 128 + wm * 32 + (l >> 2);
    const int col_base = wn * 64 + (l & 3) * 2;
    #pragma unroll
    for (int mt = 0; mt < 2; ++mt) {
        #pragma unroll
        for (int nt = 0; nt < 8; ++nt) {
            const int r0 = row_base + mt * 16;
            const int cc = col_base + nt * 8;
            float* o0 = out + (size_t)r0 * COUT + cc;
            float* o1 = out + (size_t)(r0 + 8) * COUT + cc;
            *reinterpret_cast<float2*>(o0) = make_float2(acc[mt][nt][0], acc[mt][nt][1]);
            *reinterpret_cast<float2*>(o1) = make_float2(acc[mt][nt][2], acc[mt][nt][3]);
        }
    }
}

// ---------------- launch ----------------
extern "C" void kernel_launch(void* const* d_in, const int* in_sizes, int n_in,
                              void* d_out, int out_size)
{
    const float* feats  = (const float*)d_in[0];
    const float* weight = (const float*)d_in[1];
    const float* alpha  = (const float*)d_in[2];
    float* out = (float*)d_out;

    cudaFuncSetAttribute(conv_mma_kernel,
                         cudaFuncAttributeMaxDynamicSharedMemorySize, SMEM_TOTAL);

    prep_kernel<<<A4_BLOCKS + W_BLOCKS + C_BLOCKS, 256>>>(feats, weight, alpha, out);
    dim3 grid(M_TOTAL / BM, 1);    // 256 CTAs
    conv_mma_kernel<<<grid, NTHREADS, SMEM_TOTAL>>>(out);
}